// round 5
// baseline (speedup 1.0000x reference)
#include <cuda_runtime.h>
#include <math.h>

#define BATCH 16
#define CH    256
#define NSP   1024      // H*W
#define NH    2
#define HD    128
#define NG    4
#define CPG   64        // channels per group

// ---------------- scratch (static device globals; no allocation) -------------
__device__ float g_scale[BATCH*CH];        // per (b,c) affine scale after GN
__device__ float g_bias [BATCH*CH];        // per (b,c) affine bias  after GN
__device__ float g_q[BATCH*CH*NSP];
__device__ float g_k[BATCH*CH*NSP];
__device__ float g_v[BATCH*CH*NSP];
__device__ float g_o[BATCH*CH*NSP];

// ---------------- 1) GroupNorm stats -> per-channel scale/bias ---------------
__global__ void gn_stats_kernel(const float* __restrict__ x,
                                const float* __restrict__ gn_w,
                                const float* __restrict__ gn_b) {
    int bg = blockIdx.x;               // 0..63
    int b = bg / NG, g = bg % NG;
    const float* xp = x + ((size_t)b*CH + (size_t)g*CPG)*NSP;
    int tid = threadIdx.x;

    float s = 0.f, s2 = 0.f;
    for (int i = tid; i < CPG*NSP; i += 256) {
        float v = xp[i];
        s += v; s2 += v*v;
    }
    __shared__ float ss[256], ss2[256];
    ss[tid] = s; ss2[tid] = s2;
    __syncthreads();
    for (int o = 128; o > 0; o >>= 1) {
        if (tid < o) { ss[tid] += ss[tid+o]; ss2[tid] += ss2[tid+o]; }
        __syncthreads();
    }
    __shared__ float sh_mean, sh_rstd;
    if (tid == 0) {
        const float inv = 1.0f / (float)(CPG*NSP);
        float mean = ss[0] * inv;
        float var  = ss2[0] * inv - mean*mean;
        sh_mean = mean;
        sh_rstd = rsqrtf(var + 1e-5f);
    }
    __syncthreads();
    if (tid < CPG) {
        int c = g*CPG + tid;
        float sc = sh_rstd * gn_w[c];
        g_scale[b*CH + c] = sc;
        g_bias [b*CH + c] = gn_b[c] - sh_mean * sc;
    }
}

// ---------------- 2) fused GN-apply + QKV GEMM -------------------------------
// q/k/v[b,o,n] = sum_c W[o,c] * (scale[b,c]*x[b,c,n] + bias[b,c])
__global__ void qkv_gemm_kernel(const float* __restrict__ x,
                                const float* __restrict__ wq,
                                const float* __restrict__ wk,
                                const float* __restrict__ wv) {
    int b  = blockIdx.z;
    int m0 = blockIdx.y * 64;
    int n0 = blockIdx.x * 64;
    int tid = threadIdx.x;

    __shared__ float As[3][16][64];   // [w][k][m]
    __shared__ float Bs[16][64];      // [k][n]

    const float* W0 = wq; const float* W1 = wk; const float* W2 = wv;

    float acc[3][4][4];
    #pragma unroll
    for (int w = 0; w < 3; w++)
        #pragma unroll
        for (int i = 0; i < 4; i++)
            #pragma unroll
            for (int j = 0; j < 4; j++) acc[w][i][j] = 0.f;

    int arow = tid >> 2;          // m within tile (0..63)
    int acol = (tid & 3) * 4;     // k (0..15)
    int brow = tid >> 4;          // k (0..15)
    int bcol = (tid & 15) * 4;    // n (0..63)
    int ty = tid >> 4, tx = tid & 15;

    const float* xb  = x + (size_t)b*CH*NSP;
    const float* scp = g_scale + b*CH;
    const float* bip = g_bias  + b*CH;

    for (int k0 = 0; k0 < CH; k0 += 16) {
        {
            float4 a0 = *(const float4*)&W0[(size_t)(m0+arow)*CH + k0 + acol];
            float4 a1 = *(const float4*)&W1[(size_t)(m0+arow)*CH + k0 + acol];
            float4 a2 = *(const float4*)&W2[(size_t)(m0+arow)*CH + k0 + acol];
            As[0][acol+0][arow]=a0.x; As[0][acol+1][arow]=a0.y; As[0][acol+2][arow]=a0.z; As[0][acol+3][arow]=a0.w;
            As[1][acol+0][arow]=a1.x; As[1][acol+1][arow]=a1.y; As[1][acol+2][arow]=a1.z; As[1][acol+3][arow]=a1.w;
            As[2][acol+0][arow]=a2.x; As[2][acol+1][arow]=a2.y; As[2][acol+2][arow]=a2.z; As[2][acol+3][arow]=a2.w;
        }
        {
            int k = k0 + brow;
            float4 bv = *(const float4*)&xb[(size_t)k*NSP + n0 + bcol];
            float s = scp[k], bi = bip[k];
            bv.x = fmaf(bv.x, s, bi);
            bv.y = fmaf(bv.y, s, bi);
            bv.z = fmaf(bv.z, s, bi);
            bv.w = fmaf(bv.w, s, bi);
            *(float4*)&Bs[brow][bcol] = bv;
        }
        __syncthreads();
        #pragma unroll
        for (int kk = 0; kk < 16; kk++) {
            float4 bv = *(const float4*)&Bs[kk][tx*4];
            #pragma unroll
            for (int w = 0; w < 3; w++) {
                float4 av = *(const float4*)&As[w][kk][ty*4];
                acc[w][0][0]=fmaf(av.x,bv.x,acc[w][0][0]); acc[w][0][1]=fmaf(av.x,bv.y,acc[w][0][1]);
                acc[w][0][2]=fmaf(av.x,bv.z,acc[w][0][2]); acc[w][0][3]=fmaf(av.x,bv.w,acc[w][0][3]);
                acc[w][1][0]=fmaf(av.y,bv.x,acc[w][1][0]); acc[w][1][1]=fmaf(av.y,bv.y,acc[w][1][1]);
                acc[w][1][2]=fmaf(av.y,bv.z,acc[w][1][2]); acc[w][1][3]=fmaf(av.y,bv.w,acc[w][1][3]);
                acc[w][2][0]=fmaf(av.z,bv.x,acc[w][2][0]); acc[w][2][1]=fmaf(av.z,bv.y,acc[w][2][1]);
                acc[w][2][2]=fmaf(av.z,bv.z,acc[w][2][2]); acc[w][2][3]=fmaf(av.z,bv.w,acc[w][2][3]);
                acc[w][3][0]=fmaf(av.w,bv.x,acc[w][3][0]); acc[w][3][1]=fmaf(av.w,bv.y,acc[w][3][1]);
                acc[w][3][2]=fmaf(av.w,bv.z,acc[w][3][2]); acc[w][3][3]=fmaf(av.w,bv.w,acc[w][3][3]);
            }
        }
        __syncthreads();
    }

    #pragma unroll
    for (int i = 0; i < 4; i++) {
        size_t base = ((size_t)b*CH + m0 + ty*4 + i)*NSP + n0 + tx*4;
        *(float4*)&g_q[base] = make_float4(acc[0][i][0],acc[0][i][1],acc[0][i][2],acc[0][i][3]);
        *(float4*)&g_k[base] = make_float4(acc[1][i][0],acc[1][i][1],acc[1][i][2],acc[1][i][3]);
        *(float4*)&g_v[base] = make_float4(acc[2][i][0],acc[2][i][1],acc[2][i][2],acc[2][i][3]);
    }
}

// ---------------- 3) fused flash attention (scores+softmax+PV) ---------------
// For one (b,h) and 64 query positions i0..i0+63:
//   S[i][j] = scale * sum_c q[c,i] k[c,j]   (c = 0..127)
//   online softmax over j, O[c][i] = sum_j V[c][j] P[i][j]
// 256 threads. Dynamic SMEM layout (stride 68 floats to dodge bank conflicts):
//   Qs[128][68], KV[128][68] (K then V per tile), Ss[64][68], Ps[64][68],
//   m[64], l[64], alpha[64]
#define SQS 68
#define FL_SMEM_FLOATS (128*SQS + 128*SQS + 64*SQS + 64*SQS + 192)
#define FL_SMEM_BYTES  (FL_SMEM_FLOATS*4)

__global__ void __launch_bounds__(256, 2) flash_kernel() {
    extern __shared__ float sm[];
    float* Qs   = sm;                      // [128][SQS]
    float* KV   = Qs + 128*SQS;            // [128][SQS]
    float* Ss   = KV + 128*SQS;            // [64][SQS]
    float* Ps   = Ss + 64*SQS;             // [64][SQS]  (P transposed: [j][i])
    float* mrow = Ps + 64*SQS;             // [64]
    float* lrow = mrow + 64;               // [64]
    float* arow = lrow + 64;               // [64]

    const int bh = blockIdx.y;             // 0..31
    const int b  = bh >> 1, h = bh & 1;
    const int i0 = blockIdx.x * 64;
    const int tid = threadIdx.x;
    const int ty = tid >> 4, tx = tid & 15;

    const size_t hdbase = ((size_t)b*CH + (size_t)h*HD)*NSP;
    const float* qp = g_q + hdbase;
    const float* kp = g_k + hdbase;
    const float* vp = g_v + hdbase;

    const float scale = 0.044194173824159216f;   // (256*2)^-0.5

    // load Q tile: Qs[c][i]
    {
        int c = ty, col4 = tx * 4;
        #pragma unroll
        for (int r = 0; r < 8; r++, c += 16)
            *(float4*)&Qs[c*SQS + col4] = *(const float4*)&qp[(size_t)c*NSP + i0 + col4];
    }
    if (tid < 64) { mrow[tid] = -1e30f; lrow[tid] = 0.f; }

    float Oacc[8][4];                      // c = ty*8+cc, i = tx*4+ii
    #pragma unroll
    for (int cc = 0; cc < 8; cc++)
        #pragma unroll
        for (int ii = 0; ii < 4; ii++) Oacc[cc][ii] = 0.f;

    __syncthreads();

    const int srow = tid >> 2;             // softmax row (0..63)
    const int sq   = tid & 3;              // quarter of the row

    for (int j0 = 0; j0 < NSP; j0 += 64) {
        // ---- load K tile into KV ----
        {
            int c = ty, col4 = tx * 4;
            #pragma unroll
            for (int r = 0; r < 8; r++, c += 16)
                *(float4*)&KV[c*SQS + col4] = *(const float4*)&kp[(size_t)c*NSP + j0 + col4];
        }
        __syncthreads();

        // ---- S = scale * Q^T K ----
        float acc[4][4];
        #pragma unroll
        for (int i = 0; i < 4; i++)
            #pragma unroll
            for (int j = 0; j < 4; j++) acc[i][j] = 0.f;

        #pragma unroll 8
        for (int c = 0; c < HD; c++) {
            float4 q4 = *(const float4*)&Qs[c*SQS + ty*4];
            float4 k4 = *(const float4*)&KV[c*SQS + tx*4];
            acc[0][0]=fmaf(q4.x,k4.x,acc[0][0]); acc[0][1]=fmaf(q4.x,k4.y,acc[0][1]);
            acc[0][2]=fmaf(q4.x,k4.z,acc[0][2]); acc[0][3]=fmaf(q4.x,k4.w,acc[0][3]);
            acc[1][0]=fmaf(q4.y,k4.x,acc[1][0]); acc[1][1]=fmaf(q4.y,k4.y,acc[1][1]);
            acc[1][2]=fmaf(q4.y,k4.z,acc[1][2]); acc[1][3]=fmaf(q4.y,k4.w,acc[1][3]);
            acc[2][0]=fmaf(q4.z,k4.x,acc[2][0]); acc[2][1]=fmaf(q4.z,k4.y,acc[2][1]);
            acc[2][2]=fmaf(q4.z,k4.z,acc[2][2]); acc[2][3]=fmaf(q4.z,k4.w,acc[2][3]);
            acc[3][0]=fmaf(q4.w,k4.x,acc[3][0]); acc[3][1]=fmaf(q4.w,k4.y,acc[3][1]);
            acc[3][2]=fmaf(q4.w,k4.z,acc[3][2]); acc[3][3]=fmaf(q4.w,k4.w,acc[3][3]);
        }
        #pragma unroll
        for (int i = 0; i < 4; i++)
            *(float4*)&Ss[(ty*4+i)*SQS + tx*4] =
                make_float4(acc[i][0]*scale, acc[i][1]*scale, acc[i][2]*scale, acc[i][3]*scale);
        __syncthreads();   // Ss ready; everyone done reading K tile

        // ---- load V tile into KV (overwrites K) ----
        {
            int c = ty, col4 = tx * 4;
            #pragma unroll
            for (int r = 0; r < 8; r++, c += 16)
                *(float4*)&KV[c*SQS + col4] = *(const float4*)&vp[(size_t)c*NSP + j0 + col4];
        }

        // ---- online softmax for 16 entries of one row ----
        {
            float4 v0 = *(const float4*)&Ss[srow*SQS + sq*16 + 0];
            float4 v1 = *(const float4*)&Ss[srow*SQS + sq*16 + 4];
            float4 v2 = *(const float4*)&Ss[srow*SQS + sq*16 + 8];
            float4 v3 = *(const float4*)&Ss[srow*SQS + sq*16 + 12];
            float mloc = fmaxf(fmaxf(fmaxf(v0.x,v0.y),fmaxf(v0.z,v0.w)),
                               fmaxf(fmaxf(v1.x,v1.y),fmaxf(v1.z,v1.w)));
            mloc = fmaxf(mloc, fmaxf(fmaxf(fmaxf(v2.x,v2.y),fmaxf(v2.z,v2.w)),
                                     fmaxf(fmaxf(v3.x,v3.y),fmaxf(v3.z,v3.w))));
            mloc = fmaxf(mloc, __shfl_xor_sync(0xffffffffu, mloc, 1));
            mloc = fmaxf(mloc, __shfl_xor_sync(0xffffffffu, mloc, 2));
            float mold = mrow[srow];
            float mnew = fmaxf(mold, mloc);

            float p[16];
            p[0]=__expf(v0.x-mnew); p[1]=__expf(v0.y-mnew); p[2]=__expf(v0.z-mnew); p[3]=__expf(v0.w-mnew);
            p[4]=__expf(v1.x-mnew); p[5]=__expf(v1.y-mnew); p[6]=__expf(v1.z-mnew); p[7]=__expf(v1.w-mnew);
            p[8]=__expf(v2.x-mnew); p[9]=__expf(v2.y-mnew); p[10]=__expf(v2.z-mnew); p[11]=__expf(v2.w-mnew);
            p[12]=__expf(v3.x-mnew); p[13]=__expf(v3.y-mnew); p[14]=__expf(v3.z-mnew); p[15]=__expf(v3.w-mnew);
            float sum = 0.f;
            #pragma unroll
            for (int k = 0; k < 16; k++) {
                Ps[(sq*16 + k)*SQS + srow] = p[k];    // transpose: Ps[j][i]
                sum += p[k];
            }
            sum += __shfl_xor_sync(0xffffffffu, sum, 1);
            sum += __shfl_xor_sync(0xffffffffu, sum, 2);
            if (sq == 0) {
                float al = __expf(mold - mnew);
                arow[srow] = al;
                mrow[srow] = mnew;
                lrow[srow] = lrow[srow]*al + sum;
            }
        }
        __syncthreads();   // Ps, alpha, V all ready

        // ---- rescale O, accumulate O += V * P^T ----
        {
            float a0 = arow[tx*4+0], a1 = arow[tx*4+1], a2 = arow[tx*4+2], a3 = arow[tx*4+3];
            #pragma unroll
            for (int cc = 0; cc < 8; cc++) {
                Oacc[cc][0] *= a0; Oacc[cc][1] *= a1; Oacc[cc][2] *= a2; Oacc[cc][3] *= a3;
            }
        }
        #pragma unroll 4
        for (int j4 = 0; j4 < 64; j4 += 4) {
            float4 p0 = *(const float4*)&Ps[(j4+0)*SQS + tx*4];
            float4 p1 = *(const float4*)&Ps[(j4+1)*SQS + tx*4];
            float4 p2 = *(const float4*)&Ps[(j4+2)*SQS + tx*4];
            float4 p3 = *(const float4*)&Ps[(j4+3)*SQS + tx*4];
            #pragma unroll
            for (int cc = 0; cc < 8; cc++) {
                float4 v4 = *(const float4*)&KV[(ty*8+cc)*SQS + j4];
                Oacc[cc][0] = fmaf(v4.x,p0.x, fmaf(v4.y,p1.x, fmaf(v4.z,p2.x, fmaf(v4.w,p3.x, Oacc[cc][0]))));
                Oacc[cc][1] = fmaf(v4.x,p0.y, fmaf(v4.y,p1.y, fmaf(v4.z,p2.y, fmaf(v4.w,p3.y, Oacc[cc][1]))));
                Oacc[cc][2] = fmaf(v4.x,p0.z, fmaf(v4.y,p1.z, fmaf(v4.z,p2.z, fmaf(v4.w,p3.z, Oacc[cc][2]))));
                Oacc[cc][3] = fmaf(v4.x,p0.w, fmaf(v4.y,p1.w, fmaf(v4.z,p2.w, fmaf(v4.w,p3.w, Oacc[cc][3]))));
            }
        }
        __syncthreads();   // done with Ps / V before next tile overwrites
    }

    // ---- epilogue: divide by l and store ----
    float i0inv = 1.0f / lrow[tx*4+0];
    float i1inv = 1.0f / lrow[tx*4+1];
    float i2inv = 1.0f / lrow[tx*4+2];
    float i3inv = 1.0f / lrow[tx*4+3];
    #pragma unroll
    for (int cc = 0; cc < 8; cc++) {
        size_t base = hdbase + (size_t)(ty*8+cc)*NSP + i0 + tx*4;
        *(float4*)&g_o[base - hdbase + hdbase] = make_float4(
            Oacc[cc][0]*i0inv, Oacc[cc][1]*i1inv, Oacc[cc][2]*i2inv, Oacc[cc][3]*i3inv);
    }
}

// ---------------- 4) proj GEMM + residual ------------------------------------
// out[b,o,n] = sum_c wp[o,c] * g_o[b,c,n] + x[b,o,n]
__global__ void proj_kernel(const float* __restrict__ x,
                            const float* __restrict__ wp,
                            float* __restrict__ out) {
    int b  = blockIdx.z;
    int m0 = blockIdx.y * 64;
    int n0 = blockIdx.x * 64;
    int tid = threadIdx.x;

    __shared__ float As[16][64];    // [k][m]
    __shared__ float Bs[16][64];    // [k][n]

    float acc[4][4];
    #pragma unroll
    for (int i=0;i<4;i++)
        #pragma unroll
        for (int j=0;j<4;j++) acc[i][j]=0.f;

    int arow = tid >> 2;
    int acol = (tid & 3) * 4;
    int brow = tid >> 4;
    int bcol = (tid & 15) * 4;
    int ty = tid >> 4, tx = tid & 15;

    const float* ob = g_o + (size_t)b*CH*NSP;

    for (int k0 = 0; k0 < CH; k0 += 16) {
        {
            float4 av = *(const float4*)&wp[(size_t)(m0+arow)*CH + k0 + acol];
            As[acol+0][arow]=av.x; As[acol+1][arow]=av.y; As[acol+2][arow]=av.z; As[acol+3][arow]=av.w;
        }
        *(float4*)&Bs[brow][bcol] = *(const float4*)&ob[(size_t)(k0+brow)*NSP + n0 + bcol];
        __syncthreads();
        #pragma unroll
        for (int kk = 0; kk < 16; kk++) {
            float4 av = *(const float4*)&As[kk][ty*4];
            float4 bv = *(const float4*)&Bs[kk][tx*4];
            acc[0][0]=fmaf(av.x,bv.x,acc[0][0]); acc[0][1]=fmaf(av.x,bv.y,acc[0][1]);
            acc[0][2]=fmaf(av.x,bv.z,acc[0][2]); acc[0][3]=fmaf(av.x,bv.w,acc[0][3]);
            acc[1][0]=fmaf(av.y,bv.x,acc[1][0]); acc[1][1]=fmaf(av.y,bv.y,acc[1][1]);
            acc[1][2]=fmaf(av.y,bv.z,acc[1][2]); acc[1][3]=fmaf(av.y,bv.w,acc[1][3]);
            acc[2][0]=fmaf(av.z,bv.x,acc[2][0]); acc[2][1]=fmaf(av.z,bv.y,acc[2][1]);
            acc[2][2]=fmaf(av.z,bv.z,acc[2][2]); acc[2][3]=fmaf(av.z,bv.w,acc[2][3]);
            acc[3][0]=fmaf(av.w,bv.x,acc[3][0]); acc[3][1]=fmaf(av.w,bv.y,acc[3][1]);
            acc[3][2]=fmaf(av.w,bv.z,acc[3][2]); acc[3][3]=fmaf(av.w,bv.w,acc[3][3]);
        }
        __syncthreads();
    }

    #pragma unroll
    for (int i = 0; i < 4; i++) {
        size_t base = ((size_t)b*CH + m0 + ty*4 + i)*NSP + n0 + tx*4;
        float4 r = *(const float4*)&x[base];
        *(float4*)&out[base] = make_float4(acc[i][0]+r.x, acc[i][1]+r.y,
                                           acc[i][2]+r.z, acc[i][3]+r.w);
    }
}

// -----------------------------------------------------------------------------
extern "C" void kernel_launch(void* const* d_in, const int* in_sizes, int n_in,
                              void* d_out, int out_size) {
    const float* x    = (const float*)d_in[0];
    const float* gn_w = (const float*)d_in[1];
    const float* gn_b = (const float*)d_in[2];
    const float* wq   = (const float*)d_in[3];
    const float* wk   = (const float*)d_in[4];
    const float* wv   = (const float*)d_in[5];
    const float* wp   = (const float*)d_in[6];
    float* out        = (float*)d_out;

    static bool attr_done = false;
    if (!attr_done) {
        cudaFuncSetAttribute(flash_kernel,
                             cudaFuncAttributeMaxDynamicSharedMemorySize,
                             FL_SMEM_BYTES);
        attr_done = true;
    }

    gn_stats_kernel<<<BATCH*NG, 256>>>(x, gn_w, gn_b);
    qkv_gemm_kernel<<<dim3(NSP/64, CH/64, BATCH), 256>>>(x, wq, wk, wv);
    flash_kernel<<<dim3(NSP/64, BATCH*NH), 256, FL_SMEM_BYTES>>>();
    proj_kernel<<<dim3(NSP/64, CH/64, BATCH), 256>>>(x, wp, out);
}